// round 9
// baseline (speedup 1.0000x reference)
#include <cuda_runtime.h>
#include <math.h>

// ---------------------------------------------------------------------------
// MS-SSIM, 5 levels, [16,3,512,512] f32.
// u=x+y, v=x-y (4 blurred fields U,V,UU,VV), separable 11-tap blur.
// R9: 8 cols/thread h-pass and 8 rows/thread v-pass (window amortization
// cuts LDS.128 per output from 5.25 to 3.4); h4 odd row stride (33) +
// swizzles keep every phase bank-conflict-free. Pool fused.
// ---------------------------------------------------------------------------

#define NPLANES 48
#define HALO 5
#define TW 32
#define INW 42
#define INWP 44        // float2 per row (352B)
#define HS 33          // h4 row stride in float4 (odd -> row offset 1 group)

#define G0 0.001028380f
#define G1 0.007598758f
#define G2 0.036000770f
#define G3 0.109360700f
#define G4 0.213005550f
#define G5 0.266011740f

__device__ __forceinline__ float gw(int k) {
    switch (k) {
        case 0: case 10: return G0;
        case 1: case 9:  return G1;
        case 2: case 8:  return G2;
        case 3: case 7:  return G3;
        case 4: case 6:  return G4;
        default:         return G5;
    }
}

// 16B-granule swizzle within an s_uv row
__device__ __forceinline__ int swzg(int g) { return g ^ ((g >> 3) & 1); }
__device__ __forceinline__ int suv_idx(int r, int c) {
    int g = swzg(c >> 1);
    return r * INWP + (g << 1) + (c & 1);
}
// h4 column swizzle (bijective on 0..31)
__device__ __forceinline__ int swzc(int col) { return col ^ (col >> 2); }

#define C1F 0.0001f
#define C2F 0.0009f

__device__ double g_sums[10];

#define OFF_L1 0
#define OFF_L2 3145728
#define OFF_L3 3932160
#define OFF_L4 4128768
#define SCR_TOTAL 4177920
__device__ float g_scr1[SCR_TOTAL];
__device__ float g_scr2[SCR_TOTAL];

__global__ void zero_sums_kernel() {
    if (threadIdx.x < 10) g_sums[threadIdx.x] = 0.0;
}

// One block = TH x 32 output tile. NT threads.
// Dynamic smem: s_uv (INH*INWP float2) then h4 (INH*HS float4).
template<int TH, int NT, int MINBLK>
__global__ void __launch_bounds__(NT, MINBLK)
ssim_level_kernel(const float* __restrict__ img1, const float* __restrict__ img2,
                  float* __restrict__ pool1, float* __restrict__ pool2,
                  int H, int W, int level)
{
    constexpr int INH = TH + 10;
    constexpr int HTASKS = INH * 4;   // 8 cols per task
    constexpr int VTASKS = TH * 4;    // 8 rows per task
    extern __shared__ __align__(16) char smem_dyn[];
    float2* s_uv = (float2*)smem_dyn;
    float4* h4   = (float4*)(smem_dyn + INH * INWP * sizeof(float2));
    __shared__ float red_s[NT / 32], red_c[NT / 32];

    const int plane = blockIdx.z;
    const int x0 = blockIdx.x * TW;
    const int y0 = blockIdx.y * TH;
    const float* p1 = img1 + (size_t)plane * H * W;
    const float* p2 = img2 + (size_t)plane * H * W;
    const int t = threadIdx.x;

    // ---- stage (+halo), u=a+b, v=a-b; interior fast path ----
    const bool interior = (x0 >= HALO) && (y0 >= HALO) &&
                          (x0 + TW + HALO <= W) && (y0 + TH + HALO <= H);
    if (interior) {
        for (int idx = t; idx < INH * INW; idx += NT) {
            int r = idx / INW, c = idx - r * INW;
            int gi = (y0 + r - HALO) * W + (x0 + c - HALO);
            float a = __ldg(p1 + gi);
            float b = __ldg(p2 + gi);
            s_uv[suv_idx(r, c)] = make_float2(a + b, a - b);
        }
    } else {
        for (int idx = t; idx < INH * INW; idx += NT) {
            int r = idx / INW, c = idx - r * INW;
            int gy = y0 + r - HALO;
            int gx = x0 + c - HALO;
            float a = 0.f, b = 0.f;
            if (gy >= 0 && gy < H && gx >= 0 && gx < W) {
                int gi = gy * W + gx;
                a = __ldg(p1 + gi);
                b = __ldg(p2 + gi);
            }
            s_uv[suv_idx(r, c)] = make_float2(a + b, a - b);
        }
    }
    __syncthreads();

    // ---- fused 2x2 pool of interior (TH x 32 -> TH/2 x 16): TH*8 tasks ----
    if (pool1 && t < TH * 8) {
        int i = t >> 4, j = t & 15;
        int r0 = HALO + 2 * i, c0 = HALO + 2 * j;
        float2 q00 = s_uv[suv_idx(r0, c0)];
        float2 q01 = s_uv[suv_idx(r0, c0 + 1)];
        float2 q10 = s_uv[suv_idx(r0 + 1, c0)];
        float2 q11 = s_uv[suv_idx(r0 + 1, c0 + 1)];
        float su = (q00.x + q01.x) + (q10.x + q11.x);
        float sv = (q00.y + q01.y) + (q10.y + q11.y);
        int W2 = W >> 1;
        size_t oi = (size_t)plane * (W2 * (H >> 1)) + ((y0 >> 1) + i) * W2 + (x0 >> 1) + j;
        pool1[oi] = 0.125f * (su + sv);
        pool2[oi] = 0.125f * (su - sv);
    }

    // ---- horizontal pass: INH rows x 4 groups of 8 cols ----
    if (t < HTASKS) {
        const int r   = t >> 2;
        const int grp = t & 3;
        const int gbase = grp << 2;              // first granule of 18-col window
        const float4* s_uv4 = (const float4*)s_uv;
        const int rowb = r * (INWP >> 1);

        float aU[8], aV[8], aP[8], aQ[8];
        #pragma unroll
        for (int j = 0; j < 8; j++) { aU[j] = aV[j] = aP[j] = aQ[j] = 0.f; }

        #pragma unroll
        for (int kk = 0; kk < 9; kk++) {
            float4 q = s_uv4[rowb + swzg(gbase + kk)];   // two (u,v) pairs
            #pragma unroll
            for (int h = 0; h < 2; h++) {
                const int k = 2 * kk + h;                // window pos 0..17
                float u = h ? q.z : q.x;
                float v = h ? q.w : q.y;
                float uu = u * u;
                float vv = v * v;
                #pragma unroll
                for (int j = 0; j < 8; j++) {
                    const int ki = k - j;
                    if (ki >= 0 && ki <= 10) {
                        const float w = gw(ki);
                        aU[j] = fmaf(w, u,  aU[j]);
                        aV[j] = fmaf(w, v,  aV[j]);
                        aP[j] = fmaf(w, uu, aP[j]);
                        aQ[j] = fmaf(w, vv, aQ[j]);
                    }
                }
            }
        }
        const int cbase = grp << 3;
        #pragma unroll
        for (int j = 0; j < 8; j++)
            h4[r * HS + swzc(cbase + j)] = make_float4(aU[j], aV[j], aP[j], aQ[j]);
    }
    __syncthreads();

    // ---- vertical pass + epilogue: TH*4 tasks, 8 output rows each ----
    float lssim = 0.f, lcs = 0.f;
    if (t < VTASKS) {
        const int tx  = t & 31;
        const int txs = swzc(tx);
        const int rbase = (t >> 5) * 8;

        float aU[8], aV[8], aP[8], aQ[8];
        #pragma unroll
        for (int j = 0; j < 8; j++) { aU[j] = aV[j] = aP[j] = aQ[j] = 0.f; }

        #pragma unroll
        for (int k = 0; k < 18; k++) {
            float4 hv = h4[(rbase + k) * HS + txs];
            #pragma unroll
            for (int j = 0; j < 8; j++) {
                const int ki = k - j;
                if (ki >= 0 && ki <= 10) {
                    const float w = gw(ki);
                    aU[j] = fmaf(w, hv.x, aU[j]);
                    aV[j] = fmaf(w, hv.y, aV[j]);
                    aP[j] = fmaf(w, hv.z, aP[j]);
                    aQ[j] = fmaf(w, hv.w, aQ[j]);
                }
            }
        }

        #pragma unroll
        for (int j = 0; j < 8; j++) {
            float A = aU[j] * aU[j];
            float B = aV[j] * aV[j];
            float P = aP[j], Q = aQ[j];
            float num_l = 0.5f * (A - B) + C1F;
            float den_l = 0.5f * (A + B) + C1F;
            float num_c = 0.5f * ((P - Q) - (A - B)) + C2F;
            float den_c = 0.5f * ((P + Q) - (A + B)) + C2F;
            float cs = __fdividef(num_c, den_c);
            lssim += __fdividef(num_l, den_l) * cs;
            lcs   += cs;
        }
    }

    // ---- reduction over ALL warps (idle lanes contribute 0) ----
    #pragma unroll
    for (int o = 16; o > 0; o >>= 1) {
        lssim += __shfl_xor_sync(0xFFFFFFFFu, lssim, o);
        lcs   += __shfl_xor_sync(0xFFFFFFFFu, lcs,   o);
    }
    if ((t & 31) == 0) { red_s[t >> 5] = lssim; red_c[t >> 5] = lcs; }
    __syncthreads();
    if (t == 0) {
        float S = 0.f, Cc = 0.f;
        #pragma unroll
        for (int i = 0; i < NT / 32; i++) { S += red_s[i]; Cc += red_c[i]; }
        atomicAdd(&g_sums[2 * level],     (double)S);
        atomicAdd(&g_sums[2 * level + 1], (double)Cc);
    }
}

__global__ void finalize_kernel(float* __restrict__ out)
{
    const double w[5] = {0.0448, 0.2856, 0.3001, 0.2363, 0.1333};
    double res = 1.0;
    #pragma unroll
    for (int l = 0; l < 5; l++) {
        int side = 512 >> l;
        double cnt = (double)NPLANES * side * side;
        double v = (l < 4) ? (g_sums[2 * l + 1] / cnt)
                           : (g_sums[2 * l] / cnt);
        res *= pow(v, w[l]);
    }
    out[0] = (float)res;
}

extern "C" void kernel_launch(void* const* d_in, const int* in_sizes, int n_in,
                              void* d_out, int out_size)
{
    const float* img1 = (const float*)d_in[0];
    const float* img2 = (const float*)d_in[1];
    float* out = (float*)d_out;

    float *scr1 = nullptr, *scr2 = nullptr;
    cudaGetSymbolAddress((void**)&scr1, g_scr1);
    cudaGetSymbolAddress((void**)&scr2, g_scr2);

    const float* a[5];
    const float* b[5];
    a[0] = img1;            b[0] = img2;
    a[1] = scr1 + OFF_L1;   b[1] = scr2 + OFF_L1;
    a[2] = scr1 + OFF_L2;   b[2] = scr2 + OFF_L2;
    a[3] = scr1 + OFF_L3;   b[3] = scr2 + OFF_L3;
    a[4] = scr1 + OFF_L4;   b[4] = scr2 + OFF_L4;

    const int smem_big   = 74 * INWP * sizeof(float2) + 74 * HS * sizeof(float4); // 65120
    const int smem_small = 42 * INWP * sizeof(float2) + 42 * HS * sizeof(float4); // 36960

    cudaFuncSetAttribute(ssim_level_kernel<64, 512, 2>,
                         cudaFuncAttributeMaxDynamicSharedMemorySize, smem_big);
    cudaFuncSetAttribute(ssim_level_kernel<32, 256, 4>,
                         cudaFuncAttributeMaxDynamicSharedMemorySize, smem_small);

    zero_sums_kernel<<<1, 32>>>();

    for (int l = 0; l < 5; l++) {
        int side = 512 >> l;
        float* n1 = (l < 4) ? (float*)a[l + 1] : nullptr;
        float* n2 = (l < 4) ? (float*)b[l + 1] : nullptr;
        if (side >= 128) {
            dim3 grd(side / TW, side / 64, NPLANES);
            ssim_level_kernel<64, 512, 2><<<grd, 512, smem_big>>>(
                a[l], b[l], n1, n2, side, side, l);
        } else {
            dim3 grd(side / TW, side / 32, NPLANES);
            ssim_level_kernel<32, 256, 4><<<grd, 256, smem_small>>>(
                a[l], b[l], n1, n2, side, side, l);
        }
    }
    finalize_kernel<<<1, 1>>>(out);
}

// round 10
// speedup vs baseline: 1.2876x; 1.2876x over previous
#include <cuda_runtime.h>
#include <math.h>

// ---------------------------------------------------------------------------
// MS-SSIM, 5 levels, [16,3,512,512] f32.  (R10 = R8 + max smem carveout)
// u=x+y, v=x-y reformulation (4 blurred fields U,V,UU,VV), separable 11-tap
// blur, k-outer both passes, XOR bank swizzles.
// Big levels (512/256/128): 64x32 tiles, 512 thr, 64KB dyn smem, 3 blocks/SM.
// Small levels (64/32): 32x32 tiles, 384 thr.
// ---------------------------------------------------------------------------

#define NPLANES 48
#define HALO 5
#define TW 32
#define INW 42
#define INWP 44        // float2 units per row (352B)

#define G0 0.001028380f
#define G1 0.007598758f
#define G2 0.036000770f
#define G3 0.109360700f
#define G4 0.213005550f
#define G5 0.266011740f

__device__ __forceinline__ float gw(int k) {
    switch (k) {
        case 0: case 10: return G0;
        case 1: case 9:  return G1;
        case 2: case 8:  return G2;
        case 3: case 7:  return G3;
        case 4: case 6:  return G4;
        default:         return G5;
    }
}

// 16B-granule swizzle within an s_uv row
__device__ __forceinline__ int swzg(int g) { return g ^ ((g >> 3) & 1); }
__device__ __forceinline__ int suv_idx(int r, int c) {
    int g = swzg(c >> 1);
    return r * INWP + (g << 1) + (c & 1);
}
__device__ __forceinline__ int swzc(int col) { return col ^ (col >> 2); }

#define C1F 0.0001f
#define C2F 0.0009f

__device__ double g_sums[10];

#define OFF_L1 0
#define OFF_L2 3145728
#define OFF_L3 3932160
#define OFF_L4 4128768
#define SCR_TOTAL 4177920
__device__ float g_scr1[SCR_TOTAL];
__device__ float g_scr2[SCR_TOTAL];

__global__ void zero_sums_kernel() {
    if (threadIdx.x < 10) g_sums[threadIdx.x] = 0.0;
}

// One block = TH x 32 output tile. NT threads. Dynamic smem:
//   s_uv: (TH+10)*INWP float2   then   h4: (TH+10)*TW float4
template<int TH, int NT, int MINBLK>
__global__ void __launch_bounds__(NT, MINBLK)
ssim_level_kernel(const float* __restrict__ img1, const float* __restrict__ img2,
                  float* __restrict__ pool1, float* __restrict__ pool2,
                  int H, int W, int level)
{
    constexpr int INH = TH + 10;
    extern __shared__ __align__(16) char smem_dyn[];
    float2* s_uv = (float2*)smem_dyn;                                 // INH*INWP
    float4* h4   = (float4*)(smem_dyn + INH * INWP * sizeof(float2)); // INH*TW
    __shared__ float red_s[NT / 32], red_c[NT / 32];

    const int plane = blockIdx.z;
    const int x0 = blockIdx.x * TW;
    const int y0 = blockIdx.y * TH;
    const float* p1 = img1 + (size_t)plane * H * W;
    const float* p2 = img2 + (size_t)plane * H * W;
    const int t = threadIdx.x;

    // ---- stage (+halo), u=a+b, v=a-b; interior fast path ----
    const bool interior = (x0 >= HALO) && (y0 >= HALO) &&
                          (x0 + TW + HALO <= W) && (y0 + TH + HALO <= H);
    if (interior) {
        #pragma unroll
        for (int idx = t; idx < INH * INW; idx += NT) {
            int r = idx / INW, c = idx - r * INW;
            int gi = (y0 + r - HALO) * W + (x0 + c - HALO);
            float a = __ldg(p1 + gi);
            float b = __ldg(p2 + gi);
            s_uv[suv_idx(r, c)] = make_float2(a + b, a - b);
        }
    } else {
        #pragma unroll
        for (int idx = t; idx < INH * INW; idx += NT) {
            int r = idx / INW, c = idx - r * INW;
            int gy = y0 + r - HALO;
            int gx = x0 + c - HALO;
            float a = 0.f, b = 0.f;
            if (gy >= 0 && gy < H && gx >= 0 && gx < W) {
                int gi = gy * W + gx;
                a = __ldg(p1 + gi);
                b = __ldg(p2 + gi);
            }
            s_uv[suv_idx(r, c)] = make_float2(a + b, a - b);
        }
    }
    __syncthreads();

    // ---- fused 2x2 pool of interior (TH x 32 -> TH/2 x 16) ----
    if (pool1 && t < TH * 8) {
        int i = t >> 4, j = t & 15;
        int r0 = HALO + 2 * i, c0 = HALO + 2 * j;
        float2 q00 = s_uv[suv_idx(r0, c0)];
        float2 q01 = s_uv[suv_idx(r0, c0 + 1)];
        float2 q10 = s_uv[suv_idx(r0 + 1, c0)];
        float2 q11 = s_uv[suv_idx(r0 + 1, c0 + 1)];
        float su = (q00.x + q01.x) + (q10.x + q11.x);
        float sv = (q00.y + q01.y) + (q10.y + q11.y);
        int W2 = W >> 1;
        size_t oi = (size_t)plane * (W2 * (H >> 1)) + ((y0 >> 1) + i) * W2 + (x0 >> 1) + j;
        pool1[oi] = 0.125f * (su + sv);
        pool2[oi] = 0.125f * (su - sv);
    }

    // ---- horizontal pass: INH rows x 8 groups of 4 cols ----
    for (int task = t; task < INH * 8; task += NT) {
        const int r     = task >> 3;
        const int jgrp  = task & 7;
        const int cc    = jgrp << 2;
        const int gbase = jgrp << 1;
        const float4* s_uv4 = (const float4*)s_uv;
        const int rowb = r * (INWP >> 1);

        float aU[4] = {0,0,0,0}, aV[4] = {0,0,0,0};
        float aP[4] = {0,0,0,0}, aQ[4] = {0,0,0,0};

        #pragma unroll
        for (int kk = 0; kk < 7; kk++) {
            float4 q = s_uv4[rowb + swzg(gbase + kk)];
            #pragma unroll
            for (int h = 0; h < 2; h++) {
                const int k = 2 * kk + h;
                float u = h ? q.z : q.x;
                float v = h ? q.w : q.y;
                float uu = u * u;
                float vv = v * v;
                #pragma unroll
                for (int j = 0; j < 4; j++) {
                    const int ki = k - j;
                    if (ki >= 0 && ki <= 10) {
                        const float w = gw(ki);
                        aU[j] = fmaf(w, u,  aU[j]);
                        aV[j] = fmaf(w, v,  aV[j]);
                        aP[j] = fmaf(w, uu, aP[j]);
                        aQ[j] = fmaf(w, vv, aQ[j]);
                    }
                }
            }
        }
        #pragma unroll
        for (int j = 0; j < 4; j++)
            h4[r * TW + ((cc + j) ^ jgrp)] = make_float4(aU[j], aV[j], aP[j], aQ[j]);
    }
    __syncthreads();

    // ---- vertical pass + epilogue: TH*8 tasks (4 output rows each) ----
    float lssim = 0.f, lcs = 0.f;
    if (t < TH * 8) {
        const int tx  = t & 31;
        const int txs = swzc(tx);
        const int rbase = (t >> 5) * 4;

        float aU[4] = {0,0,0,0}, aV[4] = {0,0,0,0};
        float aP[4] = {0,0,0,0}, aQ[4] = {0,0,0,0};
        #pragma unroll
        for (int k = 0; k < 14; k++) {
            float4 hv = h4[(rbase + k) * TW + txs];
            #pragma unroll
            for (int j = 0; j < 4; j++) {
                const int ki = k - j;
                if (ki >= 0 && ki <= 10) {
                    const float w = gw(ki);
                    aU[j] = fmaf(w, hv.x, aU[j]);
                    aV[j] = fmaf(w, hv.y, aV[j]);
                    aP[j] = fmaf(w, hv.z, aP[j]);
                    aQ[j] = fmaf(w, hv.w, aQ[j]);
                }
            }
        }

        #pragma unroll
        for (int j = 0; j < 4; j++) {
            float A = aU[j] * aU[j];
            float B = aV[j] * aV[j];
            float P = aP[j], Q = aQ[j];
            float num_l = 0.5f * (A - B) + C1F;
            float den_l = 0.5f * (A + B) + C1F;
            float num_c = 0.5f * ((P - Q) - (A - B)) + C2F;
            float den_c = 0.5f * ((P + Q) - (A + B)) + C2F;
            float cs = __fdividef(num_c, den_c);
            lssim += __fdividef(num_l, den_l) * cs;
            lcs   += cs;
        }

        #pragma unroll
        for (int o = 16; o > 0; o >>= 1) {
            lssim += __shfl_xor_sync(0xFFFFFFFFu, lssim, o);
            lcs   += __shfl_xor_sync(0xFFFFFFFFu, lcs,   o);
        }
        if (tx == 0) { red_s[t >> 5] = lssim; red_c[t >> 5] = lcs; }
    }
    __syncthreads();
    if (t == 0) {
        float S = 0.f, Cc = 0.f;
        #pragma unroll
        for (int i = 0; i < TH / 4; i++) { S += red_s[i]; Cc += red_c[i]; }
        atomicAdd(&g_sums[2 * level],     (double)S);
        atomicAdd(&g_sums[2 * level + 1], (double)Cc);
    }
}

__global__ void finalize_kernel(float* __restrict__ out)
{
    const double w[5] = {0.0448, 0.2856, 0.3001, 0.2363, 0.1333};
    double res = 1.0;
    #pragma unroll
    for (int l = 0; l < 5; l++) {
        int side = 512 >> l;
        double cnt = (double)NPLANES * side * side;
        double v = (l < 4) ? (g_sums[2 * l + 1] / cnt)
                           : (g_sums[2 * l] / cnt);
        res *= pow(v, w[l]);
    }
    out[0] = (float)res;
}

extern "C" void kernel_launch(void* const* d_in, const int* in_sizes, int n_in,
                              void* d_out, int out_size)
{
    const float* img1 = (const float*)d_in[0];
    const float* img2 = (const float*)d_in[1];
    float* out = (float*)d_out;

    float *scr1 = nullptr, *scr2 = nullptr;
    cudaGetSymbolAddress((void**)&scr1, g_scr1);
    cudaGetSymbolAddress((void**)&scr2, g_scr2);

    const float* a[5];
    const float* b[5];
    a[0] = img1;            b[0] = img2;
    a[1] = scr1 + OFF_L1;   b[1] = scr2 + OFF_L1;
    a[2] = scr1 + OFF_L2;   b[2] = scr2 + OFF_L2;
    a[3] = scr1 + OFF_L3;   b[3] = scr2 + OFF_L3;
    a[4] = scr1 + OFF_L4;   b[4] = scr2 + OFF_L4;

    const int smem_big   = 74 * INWP * sizeof(float2) + 74 * TW * sizeof(float4); // 64064
    const int smem_small = 42 * INWP * sizeof(float2) + 42 * TW * sizeof(float4); // 36384

    cudaFuncSetAttribute(ssim_level_kernel<64, 512, 3>,
                         cudaFuncAttributeMaxDynamicSharedMemorySize, smem_big);
    cudaFuncSetAttribute(ssim_level_kernel<32, 384, 4>,
                         cudaFuncAttributeMaxDynamicSharedMemorySize, smem_small);
    // R10: request the max shared-memory carveout so 3 x 64KB blocks fit per SM.
    cudaFuncSetAttribute(ssim_level_kernel<64, 512, 3>,
                         cudaFuncAttributePreferredSharedMemoryCarveout, 100);
    cudaFuncSetAttribute(ssim_level_kernel<32, 384, 4>,
                         cudaFuncAttributePreferredSharedMemoryCarveout, 100);

    zero_sums_kernel<<<1, 32>>>();

    for (int l = 0; l < 5; l++) {
        int side = 512 >> l;
        float* n1 = (l < 4) ? (float*)a[l + 1] : nullptr;
        float* n2 = (l < 4) ? (float*)b[l + 1] : nullptr;
        if (side >= 128) {
            dim3 grd(side / TW, side / 64, NPLANES);
            ssim_level_kernel<64, 512, 3><<<grd, 512, smem_big>>>(
                a[l], b[l], n1, n2, side, side, l);
        } else {
            dim3 grd(side / TW, side / 32, NPLANES);
            ssim_level_kernel<32, 384, 4><<<grd, 384, smem_small>>>(
                a[l], b[l], n1, n2, side, side, l);
        }
    }
    finalize_kernel<<<1, 1>>>(out);
}

// round 11
// speedup vs baseline: 1.3137x; 1.0203x over previous
#include <cuda_runtime.h>
#include <math.h>

// ---------------------------------------------------------------------------
// MS-SSIM, 5 levels, [16,3,512,512] f32.  (R11 = R8 structure, small blocks)
// u=x+y, v=x-y reformulation (4 blurred fields U,V,UU,VV), separable 11-tap
// blur, k-outer both passes, XOR bank swizzles.
// 32x32 tiles, 256 threads, 6 blocks/SM: many small blocks so cross-block
// warps hide each block's __syncthreads/tail stalls. No carveout override.
// ---------------------------------------------------------------------------

#define NPLANES 48
#define HALO 5
#define TW 32
#define TH 32
#define INW 42
#define INWP 44        // float2 units per row (352B)
#define INH 42
#define NT 256

#define G0 0.001028380f
#define G1 0.007598758f
#define G2 0.036000770f
#define G3 0.109360700f
#define G4 0.213005550f
#define G5 0.266011740f

__device__ __forceinline__ float gw(int k) {
    switch (k) {
        case 0: case 10: return G0;
        case 1: case 9:  return G1;
        case 2: case 8:  return G2;
        case 3: case 7:  return G3;
        case 4: case 6:  return G4;
        default:         return G5;
    }
}

// 16B-granule swizzle within an s_uv row
__device__ __forceinline__ int swzg(int g) { return g ^ ((g >> 3) & 1); }
__device__ __forceinline__ int suv_idx(int r, int c) {
    int g = swzg(c >> 1);
    return r * INWP + (g << 1) + (c & 1);
}
__device__ __forceinline__ int swzc(int col) { return col ^ (col >> 2); }

#define C1F 0.0001f
#define C2F 0.0009f

__device__ double g_sums[10];

#define OFF_L1 0
#define OFF_L2 3145728
#define OFF_L3 3932160
#define OFF_L4 4128768
#define SCR_TOTAL 4177920
__device__ float g_scr1[SCR_TOTAL];
__device__ float g_scr2[SCR_TOTAL];

__global__ void zero_sums_kernel() {
    if (threadIdx.x < 10) g_sums[threadIdx.x] = 0.0;
}

// One block = 32x32 output tile. 256 threads, 6 blocks/SM.
__global__ void __launch_bounds__(NT, 6)
ssim_level_kernel(const float* __restrict__ img1, const float* __restrict__ img2,
                  float* __restrict__ pool1, float* __restrict__ pool2,
                  int H, int W, int level)
{
    __shared__ __align__(16) float2 s_uv[INH * INWP];  // 14.8KB
    __shared__ __align__(16) float4 h4[INH * TW];      // 21.5KB
    __shared__ float red_s[NT / 32], red_c[NT / 32];

    const int plane = blockIdx.z;
    const int x0 = blockIdx.x * TW;
    const int y0 = blockIdx.y * TH;
    const float* p1 = img1 + (size_t)plane * H * W;
    const float* p2 = img2 + (size_t)plane * H * W;
    const int t = threadIdx.x;

    // ---- stage (+halo), u=a+b, v=a-b; interior fast path ----
    const bool interior = (x0 >= HALO) && (y0 >= HALO) &&
                          (x0 + TW + HALO <= W) && (y0 + TH + HALO <= H);
    if (interior) {
        #pragma unroll
        for (int i = 0; i < 7; i++) {
            int idx = t + i * NT;
            if (idx < INH * INW) {
                int r = idx / INW, c = idx - r * INW;
                int gi = (y0 + r - HALO) * W + (x0 + c - HALO);
                float a = __ldg(p1 + gi);
                float b = __ldg(p2 + gi);
                s_uv[suv_idx(r, c)] = make_float2(a + b, a - b);
            }
        }
    } else {
        #pragma unroll
        for (int i = 0; i < 7; i++) {
            int idx = t + i * NT;
            if (idx < INH * INW) {
                int r = idx / INW, c = idx - r * INW;
                int gy = y0 + r - HALO;
                int gx = x0 + c - HALO;
                float a = 0.f, b = 0.f;
                if (gy >= 0 && gy < H && gx >= 0 && gx < W) {
                    int gi = gy * W + gx;
                    a = __ldg(p1 + gi);
                    b = __ldg(p2 + gi);
                }
                s_uv[suv_idx(r, c)] = make_float2(a + b, a - b);
            }
        }
    }
    __syncthreads();

    // ---- fused 2x2 pool of interior (32x32 -> 16x16), all 256 threads ----
    if (pool1) {
        int i = t >> 4, j = t & 15;
        int r0 = HALO + 2 * i, c0 = HALO + 2 * j;
        float2 q00 = s_uv[suv_idx(r0, c0)];
        float2 q01 = s_uv[suv_idx(r0, c0 + 1)];
        float2 q10 = s_uv[suv_idx(r0 + 1, c0)];
        float2 q11 = s_uv[suv_idx(r0 + 1, c0 + 1)];
        float su = (q00.x + q01.x) + (q10.x + q11.x);
        float sv = (q00.y + q01.y) + (q10.y + q11.y);
        int W2 = W >> 1;
        size_t oi = (size_t)plane * (W2 * (H >> 1)) + ((y0 >> 1) + i) * W2 + (x0 >> 1) + j;
        pool1[oi] = 0.125f * (su + sv);
        pool2[oi] = 0.125f * (su - sv);
    }

    // ---- horizontal pass: 42 rows x 8 groups of 4 cols = 336 tasks ----
    for (int task = t; task < INH * 8; task += NT) {
        const int r     = task >> 3;
        const int jgrp  = task & 7;
        const int cc    = jgrp << 2;
        const int gbase = jgrp << 1;
        const float4* s_uv4 = (const float4*)s_uv;
        const int rowb = r * (INWP >> 1);

        float aU[4] = {0,0,0,0}, aV[4] = {0,0,0,0};
        float aP[4] = {0,0,0,0}, aQ[4] = {0,0,0,0};

        #pragma unroll
        for (int kk = 0; kk < 7; kk++) {
            float4 q = s_uv4[rowb + swzg(gbase + kk)];
            #pragma unroll
            for (int h = 0; h < 2; h++) {
                const int k = 2 * kk + h;
                float u = h ? q.z : q.x;
                float v = h ? q.w : q.y;
                float uu = u * u;
                float vv = v * v;
                #pragma unroll
                for (int j = 0; j < 4; j++) {
                    const int ki = k - j;
                    if (ki >= 0 && ki <= 10) {
                        const float w = gw(ki);
                        aU[j] = fmaf(w, u,  aU[j]);
                        aV[j] = fmaf(w, v,  aV[j]);
                        aP[j] = fmaf(w, uu, aP[j]);
                        aQ[j] = fmaf(w, vv, aQ[j]);
                    }
                }
            }
        }
        #pragma unroll
        for (int j = 0; j < 4; j++)
            h4[r * TW + ((cc + j) ^ jgrp)] = make_float4(aU[j], aV[j], aP[j], aQ[j]);
    }
    __syncthreads();

    // ---- vertical pass + epilogue: 256 tasks, 4 output rows each ----
    float lssim = 0.f, lcs = 0.f;
    {
        const int tx  = t & 31;
        const int txs = swzc(tx);
        const int rbase = (t >> 5) * 4;

        float aU[4] = {0,0,0,0}, aV[4] = {0,0,0,0};
        float aP[4] = {0,0,0,0}, aQ[4] = {0,0,0,0};
        #pragma unroll
        for (int k = 0; k < 14; k++) {
            float4 hv = h4[(rbase + k) * TW + txs];
            #pragma unroll
            for (int j = 0; j < 4; j++) {
                const int ki = k - j;
                if (ki >= 0 && ki <= 10) {
                    const float w = gw(ki);
                    aU[j] = fmaf(w, hv.x, aU[j]);
                    aV[j] = fmaf(w, hv.y, aV[j]);
                    aP[j] = fmaf(w, hv.z, aP[j]);
                    aQ[j] = fmaf(w, hv.w, aQ[j]);
                }
            }
        }

        #pragma unroll
        for (int j = 0; j < 4; j++) {
            float A = aU[j] * aU[j];
            float B = aV[j] * aV[j];
            float P = aP[j], Q = aQ[j];
            float num_l = 0.5f * (A - B) + C1F;
            float den_l = 0.5f * (A + B) + C1F;
            float num_c = 0.5f * ((P - Q) - (A - B)) + C2F;
            float den_c = 0.5f * ((P + Q) - (A + B)) + C2F;
            float cs = __fdividef(num_c, den_c);
            lssim += __fdividef(num_l, den_l) * cs;
            lcs   += cs;
        }

        #pragma unroll
        for (int o = 16; o > 0; o >>= 1) {
            lssim += __shfl_xor_sync(0xFFFFFFFFu, lssim, o);
            lcs   += __shfl_xor_sync(0xFFFFFFFFu, lcs,   o);
        }
        if (tx == 0) { red_s[t >> 5] = lssim; red_c[t >> 5] = lcs; }
    }
    __syncthreads();
    if (t == 0) {
        float S = 0.f, Cc = 0.f;
        #pragma unroll
        for (int i = 0; i < NT / 32; i++) { S += red_s[i]; Cc += red_c[i]; }
        atomicAdd(&g_sums[2 * level],     (double)S);
        atomicAdd(&g_sums[2 * level + 1], (double)Cc);
    }
}

__global__ void finalize_kernel(float* __restrict__ out)
{
    const double w[5] = {0.0448, 0.2856, 0.3001, 0.2363, 0.1333};
    double res = 1.0;
    #pragma unroll
    for (int l = 0; l < 5; l++) {
        int side = 512 >> l;
        double cnt = (double)NPLANES * side * side;
        double v = (l < 4) ? (g_sums[2 * l + 1] / cnt)
                           : (g_sums[2 * l] / cnt);
        res *= pow(v, w[l]);
    }
    out[0] = (float)res;
}

extern "C" void kernel_launch(void* const* d_in, const int* in_sizes, int n_in,
                              void* d_out, int out_size)
{
    const float* img1 = (const float*)d_in[0];
    const float* img2 = (const float*)d_in[1];
    float* out = (float*)d_out;

    float *scr1 = nullptr, *scr2 = nullptr;
    cudaGetSymbolAddress((void**)&scr1, g_scr1);
    cudaGetSymbolAddress((void**)&scr2, g_scr2);

    const float* a[5];
    const float* b[5];
    a[0] = img1;            b[0] = img2;
    a[1] = scr1 + OFF_L1;   b[1] = scr2 + OFF_L1;
    a[2] = scr1 + OFF_L2;   b[2] = scr2 + OFF_L2;
    a[3] = scr1 + OFF_L3;   b[3] = scr2 + OFF_L3;
    a[4] = scr1 + OFF_L4;   b[4] = scr2 + OFF_L4;

    zero_sums_kernel<<<1, 32>>>();

    for (int l = 0; l < 5; l++) {
        int side = 512 >> l;
        float* n1 = (l < 4) ? (float*)a[l + 1] : nullptr;
        float* n2 = (l < 4) ? (float*)b[l + 1] : nullptr;
        dim3 grd(side / TW, side / TH, NPLANES);
        ssim_level_kernel<<<grd, NT>>>(a[l], b[l], n1, n2, side, side, l);
    }
    finalize_kernel<<<1, 1>>>(out);
}

// round 12
// speedup vs baseline: 1.3661x; 1.0398x over previous
#include <cuda_runtime.h>
#include <math.h>

// ---------------------------------------------------------------------------
// MS-SSIM, 5 levels, [16,3,512,512] f32.  (R12: 3-launch pipeline)
//   1) pyramid_kernel: builds pooled L1..L4 for both images (+ zeroes sums)
//   2) ssim_all_kernel: ALL levels' SSIM tiles in one flat launch (16368 blk)
//   3) finalize_kernel
// SSIM tile kernel = R11 core: u=x+y / v=x-y (4 blurred fields), separable
// 11-tap blur, k-outer, XOR bank swizzles, 32x32 tiles, 256 threads.
// ---------------------------------------------------------------------------

#define NPLANES 48
#define HALO 5
#define TW 32
#define TH 32
#define INW 42
#define INWP 44        // float2 units per row (352B)
#define INH 42
#define NT 256

#define G0 0.001028380f
#define G1 0.007598758f
#define G2 0.036000770f
#define G3 0.109360700f
#define G4 0.213005550f
#define G5 0.266011740f

__device__ __forceinline__ float gw(int k) {
    switch (k) {
        case 0: case 10: return G0;
        case 1: case 9:  return G1;
        case 2: case 8:  return G2;
        case 3: case 7:  return G3;
        case 4: case 6:  return G4;
        default:         return G5;
    }
}

// 16B-granule swizzle within an s_uv row
__device__ __forceinline__ int swzg(int g) { return g ^ ((g >> 3) & 1); }
__device__ __forceinline__ int suv_idx(int r, int c) {
    int g = swzg(c >> 1);
    return r * INWP + (g << 1) + (c & 1);
}
__device__ __forceinline__ int swzc(int col) { return col ^ (col >> 2); }

#define C1F 0.0001f
#define C2F 0.0009f

__device__ double g_sums[10];

#define OFF_L1 0
#define OFF_L2 3145728
#define OFF_L3 3932160
#define OFF_L4 4128768
#define SCR_TOTAL 4177920
__device__ float g_scr1[SCR_TOTAL];
__device__ float g_scr2[SCR_TOTAL];

// ---------------------------------------------------------------------------
// Pyramid: each block pools a 64x64 L0 region down through L1..L4 for both
// images. grid (8,8,48), 256 threads (16x16); thread = 4x4 input patch.
// ---------------------------------------------------------------------------
__global__ void __launch_bounds__(256)
pyramid_kernel(const float* __restrict__ i1, const float* __restrict__ i2,
               float* __restrict__ a1, float* __restrict__ b1,
               float* __restrict__ a2, float* __restrict__ b2,
               float* __restrict__ a3, float* __restrict__ b3,
               float* __restrict__ a4, float* __restrict__ b4)
{
    __shared__ float sm2[2][256];
    __shared__ float sm3[2][64];

    const int t = threadIdx.x;
    const int i = t >> 4, j = t & 15;
    const int plane = blockIdx.z;
    const int x0 = blockIdx.x * 64, y0 = blockIdx.y * 64;

    if (blockIdx.x == 0 && blockIdx.y == 0 && plane == 0 && t < 10)
        g_sums[t] = 0.0;

    #pragma unroll
    for (int img = 0; img < 2; img++) {
        const float* p = (img ? i2 : i1) + (size_t)plane * 512 * 512;
        float* d1 = (img ? b1 : a1) + (size_t)plane * 256 * 256;
        float* d2 = (img ? b2 : a2) + (size_t)plane * 128 * 128;

        const int ry = y0 + 4 * i;
        const int cx = x0 + 4 * j;
        float4 q0 = *(const float4*)(p + (size_t)(ry + 0) * 512 + cx);
        float4 q1 = *(const float4*)(p + (size_t)(ry + 1) * 512 + cx);
        float4 q2 = *(const float4*)(p + (size_t)(ry + 2) * 512 + cx);
        float4 q3 = *(const float4*)(p + (size_t)(ry + 3) * 512 + cx);

        float l00 = 0.25f * ((q0.x + q0.y) + (q1.x + q1.y));
        float l01 = 0.25f * ((q0.z + q0.w) + (q1.z + q1.w));
        float l10 = 0.25f * ((q2.x + q2.y) + (q3.x + q3.y));
        float l11 = 0.25f * ((q2.z + q2.w) + (q3.z + q3.w));

        int r1 = (y0 >> 1) + 2 * i;
        int c1 = (x0 >> 1) + 2 * j;
        *(float2*)(d1 + (size_t)r1 * 256 + c1)       = make_float2(l00, l01);
        *(float2*)(d1 + (size_t)(r1 + 1) * 256 + c1) = make_float2(l10, l11);

        float v2 = 0.25f * ((l00 + l01) + (l10 + l11));
        d2[(size_t)((y0 >> 2) + i) * 128 + (x0 >> 2) + j] = v2;
        sm2[img][i * 16 + j] = v2;
    }
    __syncthreads();

    if (t < 128) {
        int img = t >> 6, id = t & 63;
        int i3 = id >> 3, j3 = id & 7;
        const float* s = sm2[img];
        float v3 = 0.25f * ((s[(2*i3)*16 + 2*j3]     + s[(2*i3)*16 + 2*j3 + 1]) +
                            (s[(2*i3+1)*16 + 2*j3]   + s[(2*i3+1)*16 + 2*j3 + 1]));
        float* d3 = (img ? b3 : a3) + (size_t)plane * 64 * 64;
        d3[(size_t)((y0 >> 3) + i3) * 64 + (x0 >> 3) + j3] = v3;
        sm3[img][i3 * 8 + j3] = v3;
    }
    __syncthreads();

    if (t < 32) {
        int img = t >> 4, id = t & 15;
        int i4 = id >> 2, j4 = id & 3;
        const float* s = sm3[img];
        float v4 = 0.25f * ((s[(2*i4)*8 + 2*j4]     + s[(2*i4)*8 + 2*j4 + 1]) +
                            (s[(2*i4+1)*8 + 2*j4]   + s[(2*i4+1)*8 + 2*j4 + 1]));
        float* d4 = (img ? b4 : a4) + (size_t)plane * 32 * 32;
        d4[(size_t)((y0 >> 4) + i4) * 32 + (x0 >> 4) + j4] = v4;
    }
}

// ---------------------------------------------------------------------------
// All-level SSIM: flat 1D grid, blockIdx.x decodes (level, plane, tile).
// blocks per level: 12288, 3072, 768, 192, 48 -> 16368 total.
// ---------------------------------------------------------------------------
__global__ void __launch_bounds__(NT, 6)
ssim_all_kernel(const float* __restrict__ a0, const float* __restrict__ b0,
                const float* __restrict__ a1, const float* __restrict__ b1,
                const float* __restrict__ a2, const float* __restrict__ b2,
                const float* __restrict__ a3, const float* __restrict__ b3,
                const float* __restrict__ a4, const float* __restrict__ b4)
{
    __shared__ __align__(16) float2 s_uv[INH * INWP];
    __shared__ __align__(16) float4 h4[INH * TW];
    __shared__ float red_s[NT / 32], red_c[NT / 32];

    const int bid = blockIdx.x;
    int level, base;
    if (bid < 12288)      { level = 0; base = 0;     }
    else if (bid < 15360) { level = 1; base = 12288; }
    else if (bid < 16128) { level = 2; base = 15360; }
    else if (bid < 16320) { level = 3; base = 16128; }
    else                  { level = 4; base = 16320; }
    const int side = 512 >> level;
    const int lw   = 4 - level;              // log2(tiles per row)
    const int rel  = bid - base;
    const int plane = rel >> (2 * lw);
    const int rem   = rel & ((1 << (2 * lw)) - 1);
    const int x0 = (rem & ((1 << lw) - 1)) << 5;
    const int y0 = (rem >> lw) << 5;

    const float* img1 = (level == 0) ? a0 : (level == 1) ? a1 :
                        (level == 2) ? a2 : (level == 3) ? a3 : a4;
    const float* img2 = (level == 0) ? b0 : (level == 1) ? b1 :
                        (level == 2) ? b2 : (level == 3) ? b3 : b4;

    const int H = side, W = side;
    const float* p1 = img1 + (size_t)plane * H * W;
    const float* p2 = img2 + (size_t)plane * H * W;
    const int t = threadIdx.x;

    // ---- stage (+halo), u=a+b, v=a-b; interior fast path ----
    const bool interior = (x0 >= HALO) && (y0 >= HALO) &&
                          (x0 + TW + HALO <= W) && (y0 + TH + HALO <= H);
    if (interior) {
        #pragma unroll
        for (int i = 0; i < 7; i++) {
            int idx = t + i * NT;
            if (idx < INH * INW) {
                int r = idx / INW, c = idx - r * INW;
                int gi = (y0 + r - HALO) * W + (x0 + c - HALO);
                float a = __ldg(p1 + gi);
                float b = __ldg(p2 + gi);
                s_uv[suv_idx(r, c)] = make_float2(a + b, a - b);
            }
        }
    } else {
        #pragma unroll
        for (int i = 0; i < 7; i++) {
            int idx = t + i * NT;
            if (idx < INH * INW) {
                int r = idx / INW, c = idx - r * INW;
                int gy = y0 + r - HALO;
                int gx = x0 + c - HALO;
                float a = 0.f, b = 0.f;
                if (gy >= 0 && gy < H && gx >= 0 && gx < W) {
                    int gi = gy * W + gx;
                    a = __ldg(p1 + gi);
                    b = __ldg(p2 + gi);
                }
                s_uv[suv_idx(r, c)] = make_float2(a + b, a - b);
            }
        }
    }
    __syncthreads();

    // ---- horizontal pass: 42 rows x 8 groups of 4 cols = 336 tasks ----
    for (int task = t; task < INH * 8; task += NT) {
        const int r     = task >> 3;
        const int jgrp  = task & 7;
        const int cc    = jgrp << 2;
        const int gbase = jgrp << 1;
        const float4* s_uv4 = (const float4*)s_uv;
        const int rowb = r * (INWP >> 1);

        float aU[4] = {0,0,0,0}, aV[4] = {0,0,0,0};
        float aP[4] = {0,0,0,0}, aQ[4] = {0,0,0,0};

        #pragma unroll
        for (int kk = 0; kk < 7; kk++) {
            float4 q = s_uv4[rowb + swzg(gbase + kk)];
            #pragma unroll
            for (int h = 0; h < 2; h++) {
                const int k = 2 * kk + h;
                float u = h ? q.z : q.x;
                float v = h ? q.w : q.y;
                float uu = u * u;
                float vv = v * v;
                #pragma unroll
                for (int j = 0; j < 4; j++) {
                    const int ki = k - j;
                    if (ki >= 0 && ki <= 10) {
                        const float w = gw(ki);
                        aU[j] = fmaf(w, u,  aU[j]);
                        aV[j] = fmaf(w, v,  aV[j]);
                        aP[j] = fmaf(w, uu, aP[j]);
                        aQ[j] = fmaf(w, vv, aQ[j]);
                    }
                }
            }
        }
        #pragma unroll
        for (int j = 0; j < 4; j++)
            h4[r * TW + ((cc + j) ^ jgrp)] = make_float4(aU[j], aV[j], aP[j], aQ[j]);
    }
    __syncthreads();

    // ---- vertical pass + epilogue: 256 tasks, 4 output rows each ----
    float lssim = 0.f, lcs = 0.f;
    {
        const int tx  = t & 31;
        const int txs = swzc(tx);
        const int rbase = (t >> 5) * 4;

        float aU[4] = {0,0,0,0}, aV[4] = {0,0,0,0};
        float aP[4] = {0,0,0,0}, aQ[4] = {0,0,0,0};
        #pragma unroll
        for (int k = 0; k < 14; k++) {
            float4 hv = h4[(rbase + k) * TW + txs];
            #pragma unroll
            for (int j = 0; j < 4; j++) {
                const int ki = k - j;
                if (ki >= 0 && ki <= 10) {
                    const float w = gw(ki);
                    aU[j] = fmaf(w, hv.x, aU[j]);
                    aV[j] = fmaf(w, hv.y, aV[j]);
                    aP[j] = fmaf(w, hv.z, aP[j]);
                    aQ[j] = fmaf(w, hv.w, aQ[j]);
                }
            }
        }

        #pragma unroll
        for (int j = 0; j < 4; j++) {
            float A = aU[j] * aU[j];
            float B = aV[j] * aV[j];
            float P = aP[j], Q = aQ[j];
            float num_l = 0.5f * (A - B) + C1F;
            float den_l = 0.5f * (A + B) + C1F;
            float num_c = 0.5f * ((P - Q) - (A - B)) + C2F;
            float den_c = 0.5f * ((P + Q) - (A + B)) + C2F;
            float cs = __fdividef(num_c, den_c);
            lssim += __fdividef(num_l, den_l) * cs;
            lcs   += cs;
        }

        #pragma unroll
        for (int o = 16; o > 0; o >>= 1) {
            lssim += __shfl_xor_sync(0xFFFFFFFFu, lssim, o);
            lcs   += __shfl_xor_sync(0xFFFFFFFFu, lcs,   o);
        }
        if (tx == 0) { red_s[t >> 5] = lssim; red_c[t >> 5] = lcs; }
    }
    __syncthreads();
    if (t == 0) {
        float S = 0.f, Cc = 0.f;
        #pragma unroll
        for (int i = 0; i < NT / 32; i++) { S += red_s[i]; Cc += red_c[i]; }
        atomicAdd(&g_sums[2 * level],     (double)S);
        atomicAdd(&g_sums[2 * level + 1], (double)Cc);
    }
}

__global__ void finalize_kernel(float* __restrict__ out)
{
    const double w[5] = {0.0448, 0.2856, 0.3001, 0.2363, 0.1333};
    double res = 1.0;
    #pragma unroll
    for (int l = 0; l < 5; l++) {
        int side = 512 >> l;
        double cnt = (double)NPLANES * side * side;
        double v = (l < 4) ? (g_sums[2 * l + 1] / cnt)
                           : (g_sums[2 * l] / cnt);
        res *= pow(v, w[l]);
    }
    out[0] = (float)res;
}

extern "C" void kernel_launch(void* const* d_in, const int* in_sizes, int n_in,
                              void* d_out, int out_size)
{
    const float* img1 = (const float*)d_in[0];
    const float* img2 = (const float*)d_in[1];
    float* out = (float*)d_out;

    float *scr1 = nullptr, *scr2 = nullptr;
    cudaGetSymbolAddress((void**)&scr1, g_scr1);
    cudaGetSymbolAddress((void**)&scr2, g_scr2);

    float* a1 = scr1 + OFF_L1;  float* b1 = scr2 + OFF_L1;
    float* a2 = scr1 + OFF_L2;  float* b2 = scr2 + OFF_L2;
    float* a3 = scr1 + OFF_L3;  float* b3 = scr2 + OFF_L3;
    float* a4 = scr1 + OFF_L4;  float* b4 = scr2 + OFF_L4;

    pyramid_kernel<<<dim3(8, 8, NPLANES), 256>>>(
        img1, img2, a1, b1, a2, b2, a3, b3, a4, b4);

    ssim_all_kernel<<<16368, NT>>>(
        img1, img2, a1, b1, a2, b2, a3, b3, a4, b4);

    finalize_kernel<<<1, 1>>>(out);
}

// round 13
// speedup vs baseline: 1.4298x; 1.0467x over previous
#include <cuda_runtime.h>
#include <math.h>

// ---------------------------------------------------------------------------
// MS-SSIM, 5 levels, [16,3,512,512] f32.  (R13: 4-step pipeline)
//   0) memsetAsync g_sums = 0
//   1) ssim_L0 kernel (12288 blk): L0 ssim sums + fused 2x2 pool -> L1
//   2) pyramid2 (768 blk): L2/L3/L4 from L1 (12.6MB read, ~3us)
//   3) ssim_rest (4080 blk flat): levels 1-4 merged
//   4) finalize
// Tile kernel core (R11): u=x+y / v=x-y, separable 11-tap blur, k-outer,
// XOR bank swizzles, 32x32 tiles, 256 threads.
// ---------------------------------------------------------------------------

#define NPLANES 48
#define HALO 5
#define TW 32
#define TH 32
#define INW 42
#define INWP 44        // float2 units per row (352B)
#define INH 42
#define NT 256

#define G0 0.001028380f
#define G1 0.007598758f
#define G2 0.036000770f
#define G3 0.109360700f
#define G4 0.213005550f
#define G5 0.266011740f

__device__ __forceinline__ float gw(int k) {
    switch (k) {
        case 0: case 10: return G0;
        case 1: case 9:  return G1;
        case 2: case 8:  return G2;
        case 3: case 7:  return G3;
        case 4: case 6:  return G4;
        default:         return G5;
    }
}

__device__ __forceinline__ int swzg(int g) { return g ^ ((g >> 3) & 1); }
__device__ __forceinline__ int suv_idx(int r, int c) {
    int g = swzg(c >> 1);
    return r * INWP + (g << 1) + (c & 1);
}
__device__ __forceinline__ int swzc(int col) { return col ^ (col >> 2); }

#define C1F 0.0001f
#define C2F 0.0009f

__device__ double g_sums[10];

#define OFF_L1 0
#define OFF_L2 3145728
#define OFF_L3 3932160
#define OFF_L4 4128768
#define SCR_TOTAL 4177920
__device__ float g_scr1[SCR_TOTAL];
__device__ float g_scr2[SCR_TOTAL];

// ---------------------------------------------------------------------------
// Shared tile routine: stages (u,v), optional pool -> next level, separable
// blur, ssim/cs partial sums -> atomics. (forceinline device function)
// ---------------------------------------------------------------------------
__device__ __forceinline__ void ssim_tile(
    const float* __restrict__ p1, const float* __restrict__ p2,
    float* __restrict__ pool1, float* __restrict__ pool2,   // may be null
    int plane, int x0, int y0, int H, int W, int level,
    float2* s_uv, float4* h4, float* red_s, float* red_c)
{
    const int t = threadIdx.x;

    const bool interior = (x0 >= HALO) && (y0 >= HALO) &&
                          (x0 + TW + HALO <= W) && (y0 + TH + HALO <= H);
    if (interior) {
        #pragma unroll
        for (int i = 0; i < 7; i++) {
            int idx = t + i * NT;
            if (idx < INH * INW) {
                int r = idx / INW, c = idx - r * INW;
                int gi = (y0 + r - HALO) * W + (x0 + c - HALO);
                float a = __ldg(p1 + gi);
                float b = __ldg(p2 + gi);
                s_uv[suv_idx(r, c)] = make_float2(a + b, a - b);
            }
        }
    } else {
        #pragma unroll
        for (int i = 0; i < 7; i++) {
            int idx = t + i * NT;
            if (idx < INH * INW) {
                int r = idx / INW, c = idx - r * INW;
                int gy = y0 + r - HALO;
                int gx = x0 + c - HALO;
                float a = 0.f, b = 0.f;
                if (gy >= 0 && gy < H && gx >= 0 && gx < W) {
                    int gi = gy * W + gx;
                    a = __ldg(p1 + gi);
                    b = __ldg(p2 + gi);
                }
                s_uv[suv_idx(r, c)] = make_float2(a + b, a - b);
            }
        }
    }
    __syncthreads();

    // fused 2x2 pool of interior (32x32 -> 16x16), all 256 threads
    if (pool1) {
        int i = t >> 4, j = t & 15;
        int r0 = HALO + 2 * i, c0 = HALO + 2 * j;
        float2 q00 = s_uv[suv_idx(r0, c0)];
        float2 q01 = s_uv[suv_idx(r0, c0 + 1)];
        float2 q10 = s_uv[suv_idx(r0 + 1, c0)];
        float2 q11 = s_uv[suv_idx(r0 + 1, c0 + 1)];
        float su = (q00.x + q01.x) + (q10.x + q11.x);
        float sv = (q00.y + q01.y) + (q10.y + q11.y);
        int W2 = W >> 1;
        size_t oi = (size_t)plane * (W2 * (H >> 1)) + ((y0 >> 1) + i) * W2 + (x0 >> 1) + j;
        pool1[oi] = 0.125f * (su + sv);
        pool2[oi] = 0.125f * (su - sv);
    }

    // horizontal pass: 42 rows x 8 groups of 4 cols = 336 tasks
    for (int task = t; task < INH * 8; task += NT) {
        const int r     = task >> 3;
        const int jgrp  = task & 7;
        const int cc    = jgrp << 2;
        const int gbase = jgrp << 1;
        const float4* s_uv4 = (const float4*)s_uv;
        const int rowb = r * (INWP >> 1);

        float aU[4] = {0,0,0,0}, aV[4] = {0,0,0,0};
        float aP[4] = {0,0,0,0}, aQ[4] = {0,0,0,0};

        #pragma unroll
        for (int kk = 0; kk < 7; kk++) {
            float4 q = s_uv4[rowb + swzg(gbase + kk)];
            #pragma unroll
            for (int h = 0; h < 2; h++) {
                const int k = 2 * kk + h;
                float u = h ? q.z : q.x;
                float v = h ? q.w : q.y;
                float uu = u * u;
                float vv = v * v;
                #pragma unroll
                for (int j = 0; j < 4; j++) {
                    const int ki = k - j;
                    if (ki >= 0 && ki <= 10) {
                        const float w = gw(ki);
                        aU[j] = fmaf(w, u,  aU[j]);
                        aV[j] = fmaf(w, v,  aV[j]);
                        aP[j] = fmaf(w, uu, aP[j]);
                        aQ[j] = fmaf(w, vv, aQ[j]);
                    }
                }
            }
        }
        #pragma unroll
        for (int j = 0; j < 4; j++)
            h4[r * TW + ((cc + j) ^ jgrp)] = make_float4(aU[j], aV[j], aP[j], aQ[j]);
    }
    __syncthreads();

    // vertical pass + epilogue: 256 tasks, 4 output rows each
    float lssim = 0.f, lcs = 0.f;
    {
        const int tx  = t & 31;
        const int txs = swzc(tx);
        const int rbase = (t >> 5) * 4;

        float aU[4] = {0,0,0,0}, aV[4] = {0,0,0,0};
        float aP[4] = {0,0,0,0}, aQ[4] = {0,0,0,0};
        #pragma unroll
        for (int k = 0; k < 14; k++) {
            float4 hv = h4[(rbase + k) * TW + txs];
            #pragma unroll
            for (int j = 0; j < 4; j++) {
                const int ki = k - j;
                if (ki >= 0 && ki <= 10) {
                    const float w = gw(ki);
                    aU[j] = fmaf(w, hv.x, aU[j]);
                    aV[j] = fmaf(w, hv.y, aV[j]);
                    aP[j] = fmaf(w, hv.z, aP[j]);
                    aQ[j] = fmaf(w, hv.w, aQ[j]);
                }
            }
        }

        #pragma unroll
        for (int j = 0; j < 4; j++) {
            float A = aU[j] * aU[j];
            float B = aV[j] * aV[j];
            float P = aP[j], Q = aQ[j];
            float num_l = 0.5f * (A - B) + C1F;
            float den_l = 0.5f * (A + B) + C1F;
            float num_c = 0.5f * ((P - Q) - (A - B)) + C2F;
            float den_c = 0.5f * ((P + Q) - (A + B)) + C2F;
            float cs = __fdividef(num_c, den_c);
            lssim += __fdividef(num_l, den_l) * cs;
            lcs   += cs;
        }

        #pragma unroll
        for (int o = 16; o > 0; o >>= 1) {
            lssim += __shfl_xor_sync(0xFFFFFFFFu, lssim, o);
            lcs   += __shfl_xor_sync(0xFFFFFFFFu, lcs,   o);
        }
        if (tx == 0) { red_s[t >> 5] = lssim; red_c[t >> 5] = lcs; }
    }
    __syncthreads();
    if (t == 0) {
        float S = 0.f, Cc = 0.f;
        #pragma unroll
        for (int i = 0; i < NT / 32; i++) { S += red_s[i]; Cc += red_c[i]; }
        atomicAdd(&g_sums[2 * level],     (double)S);
        atomicAdd(&g_sums[2 * level + 1], (double)Cc);
    }
}

// ---- Launch 1: L0 ssim + fused pool -> L1. grid (16,16,48). ----
__global__ void __launch_bounds__(NT, 6)
ssim_l0_kernel(const float* __restrict__ img1, const float* __restrict__ img2,
               float* __restrict__ pool1, float* __restrict__ pool2)
{
    __shared__ __align__(16) float2 s_uv[INH * INWP];
    __shared__ __align__(16) float4 h4[INH * TW];
    __shared__ float red_s[NT / 32], red_c[NT / 32];

    const int plane = blockIdx.z;
    ssim_tile(img1 + (size_t)plane * 512 * 512,
              img2 + (size_t)plane * 512 * 512,
              pool1, pool2, plane,
              blockIdx.x * TW, blockIdx.y * TH, 512, 512, 0,
              s_uv, h4, red_s, red_c);
}

// ---- Launch 2: pyramid L2/L3/L4 from L1. grid (4,4,48), 256 thr. ----
__global__ void __launch_bounds__(256)
pyramid2_kernel(const float* __restrict__ i1, const float* __restrict__ i2,
                float* __restrict__ a2, float* __restrict__ b2,
                float* __restrict__ a3, float* __restrict__ b3,
                float* __restrict__ a4, float* __restrict__ b4)
{
    __shared__ float sm3[2][256];   // L3 values, 16x16 per img

    const int t = threadIdx.x;
    const int i = t >> 4, j = t & 15;
    const int plane = blockIdx.z;
    const int x0 = blockIdx.x * 64, y0 = blockIdx.y * 64;   // L1 coords

    #pragma unroll
    for (int img = 0; img < 2; img++) {
        const float* p = (img ? i2 : i1) + (size_t)plane * 256 * 256;
        float* d2 = (img ? b2 : a2) + (size_t)plane * 128 * 128;
        float* d3 = (img ? b3 : a3) + (size_t)plane * 64 * 64;

        const int ry = y0 + 4 * i;
        const int cx = x0 + 4 * j;
        float4 q0 = *(const float4*)(p + (size_t)(ry + 0) * 256 + cx);
        float4 q1 = *(const float4*)(p + (size_t)(ry + 1) * 256 + cx);
        float4 q2 = *(const float4*)(p + (size_t)(ry + 2) * 256 + cx);
        float4 q3 = *(const float4*)(p + (size_t)(ry + 3) * 256 + cx);

        float l00 = 0.25f * ((q0.x + q0.y) + (q1.x + q1.y));
        float l01 = 0.25f * ((q0.z + q0.w) + (q1.z + q1.w));
        float l10 = 0.25f * ((q2.x + q2.y) + (q3.x + q3.y));
        float l11 = 0.25f * ((q2.z + q2.w) + (q3.z + q3.w));

        int r2 = (y0 >> 1) + 2 * i;
        int c2 = (x0 >> 1) + 2 * j;
        *(float2*)(d2 + (size_t)r2 * 128 + c2)       = make_float2(l00, l01);
        *(float2*)(d2 + (size_t)(r2 + 1) * 128 + c2) = make_float2(l10, l11);

        float v3 = 0.25f * ((l00 + l01) + (l10 + l11));
        d3[(size_t)((y0 >> 2) + i) * 64 + (x0 >> 2) + j] = v3;
        sm3[img][i * 16 + j] = v3;
    }
    __syncthreads();

    if (t < 128) {
        int img = t >> 6, id = t & 63;
        int i4 = id >> 3, j4 = id & 7;
        const float* s = sm3[img];
        float v4 = 0.25f * ((s[(2*i4)*16 + 2*j4]   + s[(2*i4)*16 + 2*j4 + 1]) +
                            (s[(2*i4+1)*16 + 2*j4] + s[(2*i4+1)*16 + 2*j4 + 1]));
        float* d4 = (img ? b4 : a4) + (size_t)plane * 32 * 32;
        d4[(size_t)((y0 >> 3) + i4) * 32 + (x0 >> 3) + j4] = v4;
    }
}

// ---- Launch 3: levels 1-4, flat 4080 blocks ----
__global__ void __launch_bounds__(NT, 6)
ssim_rest_kernel(const float* __restrict__ a1, const float* __restrict__ b1,
                 const float* __restrict__ a2, const float* __restrict__ b2,
                 const float* __restrict__ a3, const float* __restrict__ b3,
                 const float* __restrict__ a4, const float* __restrict__ b4)
{
    __shared__ __align__(16) float2 s_uv[INH * INWP];
    __shared__ __align__(16) float4 h4[INH * TW];
    __shared__ float red_s[NT / 32], red_c[NT / 32];

    const int bid = blockIdx.x;
    int level, base;
    if (bid < 3072)      { level = 1; base = 0;    }
    else if (bid < 3840) { level = 2; base = 3072; }
    else if (bid < 4032) { level = 3; base = 3840; }
    else                 { level = 4; base = 4032; }
    const int side = 512 >> level;
    const int lw   = 4 - level;
    const int rel  = bid - base;
    const int plane = rel >> (2 * lw);
    const int rem   = rel & ((1 << (2 * lw)) - 1);
    const int x0 = (rem & ((1 << lw) - 1)) << 5;
    const int y0 = (rem >> lw) << 5;

    const float* img1 = (level == 1) ? a1 : (level == 2) ? a2 :
                        (level == 3) ? a3 : a4;
    const float* img2 = (level == 1) ? b1 : (level == 2) ? b2 :
                        (level == 3) ? b3 : b4;

    ssim_tile(img1 + (size_t)plane * side * side,
              img2 + (size_t)plane * side * side,
              nullptr, nullptr, plane,
              x0, y0, side, side, level,
              s_uv, h4, red_s, red_c);
}

__global__ void finalize_kernel(float* __restrict__ out)
{
    const double w[5] = {0.0448, 0.2856, 0.3001, 0.2363, 0.1333};
    double res = 1.0;
    #pragma unroll
    for (int l = 0; l < 5; l++) {
        int side = 512 >> l;
        double cnt = (double)NPLANES * side * side;
        double v = (l < 4) ? (g_sums[2 * l + 1] / cnt)
                           : (g_sums[2 * l] / cnt);
        res *= pow(v, w[l]);
    }
    out[0] = (float)res;
}

extern "C" void kernel_launch(void* const* d_in, const int* in_sizes, int n_in,
                              void* d_out, int out_size)
{
    const float* img1 = (const float*)d_in[0];
    const float* img2 = (const float*)d_in[1];
    float* out = (float*)d_out;

    float *scr1 = nullptr, *scr2 = nullptr;
    cudaGetSymbolAddress((void**)&scr1, g_scr1);
    cudaGetSymbolAddress((void**)&scr2, g_scr2);
    void* sums_ptr = nullptr;
    cudaGetSymbolAddress(&sums_ptr, g_sums);

    float* a1 = scr1 + OFF_L1;  float* b1 = scr2 + OFF_L1;
    float* a2 = scr1 + OFF_L2;  float* b2 = scr2 + OFF_L2;
    float* a3 = scr1 + OFF_L3;  float* b3 = scr2 + OFF_L3;
    float* a4 = scr1 + OFF_L4;  float* b4 = scr2 + OFF_L4;

    cudaMemsetAsync(sums_ptr, 0, 10 * sizeof(double));

    ssim_l0_kernel<<<dim3(16, 16, NPLANES), NT>>>(img1, img2, a1, b1);
    pyramid2_kernel<<<dim3(4, 4, NPLANES), 256>>>(a1, b1, a2, b2, a3, b3, a4, b4);
    ssim_rest_kernel<<<4080, NT>>>(a1, b1, a2, b2, a3, b3, a4, b4);
    finalize_kernel<<<1, 1>>>(out);
}

// round 14
// speedup vs baseline: 1.5723x; 1.0997x over previous
#include <cuda_runtime.h>
#include <math.h>

// ---------------------------------------------------------------------------
// MS-SSIM, 5 levels, [16,3,512,512] f32.  (R14 = R13 + fast finalize)
//   0) memsetAsync g_sums = 0
//   1) ssim_L0 kernel (12288 blk): L0 ssim sums + fused 2x2 pool -> L1
//   2) pyramid2 (768 blk): L2/L3/L4 from L1
//   3) ssim_rest (4080 blk flat): levels 1-4 merged
//   4) finalize: fp32 exp/log warp-parallel (was 19us of serial fp64 pow!)
// Tile kernel core: u=x+y / v=x-y, separable 11-tap blur, k-outer,
// XOR bank swizzles, 32x32 tiles, 256 threads.
// ---------------------------------------------------------------------------

#define NPLANES 48
#define HALO 5
#define TW 32
#define TH 32
#define INW 42
#define INWP 44        // float2 units per row (352B)
#define INH 42
#define NT 256

#define G0 0.001028380f
#define G1 0.007598758f
#define G2 0.036000770f
#define G3 0.109360700f
#define G4 0.213005550f
#define G5 0.266011740f

__device__ __forceinline__ float gw(int k) {
    switch (k) {
        case 0: case 10: return G0;
        case 1: case 9:  return G1;
        case 2: case 8:  return G2;
        case 3: case 7:  return G3;
        case 4: case 6:  return G4;
        default:         return G5;
    }
}

__device__ __forceinline__ int swzg(int g) { return g ^ ((g >> 3) & 1); }
__device__ __forceinline__ int suv_idx(int r, int c) {
    int g = swzg(c >> 1);
    return r * INWP + (g << 1) + (c & 1);
}
__device__ __forceinline__ int swzc(int col) { return col ^ (col >> 2); }

#define C1F 0.0001f
#define C2F 0.0009f

__device__ double g_sums[10];

#define OFF_L1 0
#define OFF_L2 3145728
#define OFF_L3 3932160
#define OFF_L4 4128768
#define SCR_TOTAL 4177920
__device__ float g_scr1[SCR_TOTAL];
__device__ float g_scr2[SCR_TOTAL];

// ---------------------------------------------------------------------------
// Shared tile routine
// ---------------------------------------------------------------------------
__device__ __forceinline__ void ssim_tile(
    const float* __restrict__ p1, const float* __restrict__ p2,
    float* __restrict__ pool1, float* __restrict__ pool2,   // may be null
    int plane, int x0, int y0, int H, int W, int level,
    float2* s_uv, float4* h4, float* red_s, float* red_c)
{
    const int t = threadIdx.x;

    const bool interior = (x0 >= HALO) && (y0 >= HALO) &&
                          (x0 + TW + HALO <= W) && (y0 + TH + HALO <= H);
    if (interior) {
        #pragma unroll
        for (int i = 0; i < 7; i++) {
            int idx = t + i * NT;
            if (idx < INH * INW) {
                int r = idx / INW, c = idx - r * INW;
                int gi = (y0 + r - HALO) * W + (x0 + c - HALO);
                float a = __ldg(p1 + gi);
                float b = __ldg(p2 + gi);
                s_uv[suv_idx(r, c)] = make_float2(a + b, a - b);
            }
        }
    } else {
        #pragma unroll
        for (int i = 0; i < 7; i++) {
            int idx = t + i * NT;
            if (idx < INH * INW) {
                int r = idx / INW, c = idx - r * INW;
                int gy = y0 + r - HALO;
                int gx = x0 + c - HALO;
                float a = 0.f, b = 0.f;
                if (gy >= 0 && gy < H && gx >= 0 && gx < W) {
                    int gi = gy * W + gx;
                    a = __ldg(p1 + gi);
                    b = __ldg(p2 + gi);
                }
                s_uv[suv_idx(r, c)] = make_float2(a + b, a - b);
            }
        }
    }
    __syncthreads();

    // fused 2x2 pool of interior (32x32 -> 16x16), all 256 threads
    if (pool1) {
        int i = t >> 4, j = t & 15;
        int r0 = HALO + 2 * i, c0 = HALO + 2 * j;
        float2 q00 = s_uv[suv_idx(r0, c0)];
        float2 q01 = s_uv[suv_idx(r0, c0 + 1)];
        float2 q10 = s_uv[suv_idx(r0 + 1, c0)];
        float2 q11 = s_uv[suv_idx(r0 + 1, c0 + 1)];
        float su = (q00.x + q01.x) + (q10.x + q11.x);
        float sv = (q00.y + q01.y) + (q10.y + q11.y);
        int W2 = W >> 1;
        size_t oi = (size_t)plane * (W2 * (H >> 1)) + ((y0 >> 1) + i) * W2 + (x0 >> 1) + j;
        pool1[oi] = 0.125f * (su + sv);
        pool2[oi] = 0.125f * (su - sv);
    }

    // horizontal pass: 42 rows x 8 groups of 4 cols = 336 tasks
    for (int task = t; task < INH * 8; task += NT) {
        const int r     = task >> 3;
        const int jgrp  = task & 7;
        const int cc    = jgrp << 2;
        const int gbase = jgrp << 1;
        const float4* s_uv4 = (const float4*)s_uv;
        const int rowb = r * (INWP >> 1);

        float aU[4] = {0,0,0,0}, aV[4] = {0,0,0,0};
        float aP[4] = {0,0,0,0}, aQ[4] = {0,0,0,0};

        #pragma unroll
        for (int kk = 0; kk < 7; kk++) {
            float4 q = s_uv4[rowb + swzg(gbase + kk)];
            #pragma unroll
            for (int h = 0; h < 2; h++) {
                const int k = 2 * kk + h;
                float u = h ? q.z : q.x;
                float v = h ? q.w : q.y;
                float uu = u * u;
                float vv = v * v;
                #pragma unroll
                for (int j = 0; j < 4; j++) {
                    const int ki = k - j;
                    if (ki >= 0 && ki <= 10) {
                        const float w = gw(ki);
                        aU[j] = fmaf(w, u,  aU[j]);
                        aV[j] = fmaf(w, v,  aV[j]);
                        aP[j] = fmaf(w, uu, aP[j]);
                        aQ[j] = fmaf(w, vv, aQ[j]);
                    }
                }
            }
        }
        #pragma unroll
        for (int j = 0; j < 4; j++)
            h4[r * TW + ((cc + j) ^ jgrp)] = make_float4(aU[j], aV[j], aP[j], aQ[j]);
    }
    __syncthreads();

    // vertical pass + epilogue: 256 tasks, 4 output rows each
    float lssim = 0.f, lcs = 0.f;
    {
        const int tx  = t & 31;
        const int txs = swzc(tx);
        const int rbase = (t >> 5) * 4;

        float aU[4] = {0,0,0,0}, aV[4] = {0,0,0,0};
        float aP[4] = {0,0,0,0}, aQ[4] = {0,0,0,0};
        #pragma unroll
        for (int k = 0; k < 14; k++) {
            float4 hv = h4[(rbase + k) * TW + txs];
            #pragma unroll
            for (int j = 0; j < 4; j++) {
                const int ki = k - j;
                if (ki >= 0 && ki <= 10) {
                    const float w = gw(ki);
                    aU[j] = fmaf(w, hv.x, aU[j]);
                    aV[j] = fmaf(w, hv.y, aV[j]);
                    aP[j] = fmaf(w, hv.z, aP[j]);
                    aQ[j] = fmaf(w, hv.w, aQ[j]);
                }
            }
        }

        #pragma unroll
        for (int j = 0; j < 4; j++) {
            float A = aU[j] * aU[j];
            float B = aV[j] * aV[j];
            float P = aP[j], Q = aQ[j];
            float num_l = 0.5f * (A - B) + C1F;
            float den_l = 0.5f * (A + B) + C1F;
            float num_c = 0.5f * ((P - Q) - (A - B)) + C2F;
            float den_c = 0.5f * ((P + Q) - (A + B)) + C2F;
            float cs = __fdividef(num_c, den_c);
            lssim += __fdividef(num_l, den_l) * cs;
            lcs   += cs;
        }

        #pragma unroll
        for (int o = 16; o > 0; o >>= 1) {
            lssim += __shfl_xor_sync(0xFFFFFFFFu, lssim, o);
            lcs   += __shfl_xor_sync(0xFFFFFFFFu, lcs,   o);
        }
        if (tx == 0) { red_s[t >> 5] = lssim; red_c[t >> 5] = lcs; }
    }
    __syncthreads();
    if (t == 0) {
        float S = 0.f, Cc = 0.f;
        #pragma unroll
        for (int i = 0; i < NT / 32; i++) { S += red_s[i]; Cc += red_c[i]; }
        atomicAdd(&g_sums[2 * level],     (double)S);
        atomicAdd(&g_sums[2 * level + 1], (double)Cc);
    }
}

// ---- Launch 1: L0 ssim + fused pool -> L1. grid (16,16,48). ----
__global__ void __launch_bounds__(NT, 6)
ssim_l0_kernel(const float* __restrict__ img1, const float* __restrict__ img2,
               float* __restrict__ pool1, float* __restrict__ pool2)
{
    __shared__ __align__(16) float2 s_uv[INH * INWP];
    __shared__ __align__(16) float4 h4[INH * TW];
    __shared__ float red_s[NT / 32], red_c[NT / 32];

    const int plane = blockIdx.z;
    ssim_tile(img1 + (size_t)plane * 512 * 512,
              img2 + (size_t)plane * 512 * 512,
              pool1, pool2, plane,
              blockIdx.x * TW, blockIdx.y * TH, 512, 512, 0,
              s_uv, h4, red_s, red_c);
}

// ---- Launch 2: pyramid L2/L3/L4 from L1. grid (4,4,48), 256 thr. ----
__global__ void __launch_bounds__(256)
pyramid2_kernel(const float* __restrict__ i1, const float* __restrict__ i2,
                float* __restrict__ a2, float* __restrict__ b2,
                float* __restrict__ a3, float* __restrict__ b3,
                float* __restrict__ a4, float* __restrict__ b4)
{
    __shared__ float sm3[2][256];

    const int t = threadIdx.x;
    const int i = t >> 4, j = t & 15;
    const int plane = blockIdx.z;
    const int x0 = blockIdx.x * 64, y0 = blockIdx.y * 64;   // L1 coords

    #pragma unroll
    for (int img = 0; img < 2; img++) {
        const float* p = (img ? i2 : i1) + (size_t)plane * 256 * 256;
        float* d2 = (img ? b2 : a2) + (size_t)plane * 128 * 128;
        float* d3 = (img ? b3 : a3) + (size_t)plane * 64 * 64;

        const int ry = y0 + 4 * i;
        const int cx = x0 + 4 * j;
        float4 q0 = *(const float4*)(p + (size_t)(ry + 0) * 256 + cx);
        float4 q1 = *(const float4*)(p + (size_t)(ry + 1) * 256 + cx);
        float4 q2 = *(const float4*)(p + (size_t)(ry + 2) * 256 + cx);
        float4 q3 = *(const float4*)(p + (size_t)(ry + 3) * 256 + cx);

        float l00 = 0.25f * ((q0.x + q0.y) + (q1.x + q1.y));
        float l01 = 0.25f * ((q0.z + q0.w) + (q1.z + q1.w));
        float l10 = 0.25f * ((q2.x + q2.y) + (q3.x + q3.y));
        float l11 = 0.25f * ((q2.z + q2.w) + (q3.z + q3.w));

        int r2 = (y0 >> 1) + 2 * i;
        int c2 = (x0 >> 1) + 2 * j;
        *(float2*)(d2 + (size_t)r2 * 128 + c2)       = make_float2(l00, l01);
        *(float2*)(d2 + (size_t)(r2 + 1) * 128 + c2) = make_float2(l10, l11);

        float v3 = 0.25f * ((l00 + l01) + (l10 + l11));
        d3[(size_t)((y0 >> 2) + i) * 64 + (x0 >> 2) + j] = v3;
        sm3[img][i * 16 + j] = v3;
    }
    __syncthreads();

    if (t < 128) {
        int img = t >> 6, id = t & 63;
        int i4 = id >> 3, j4 = id & 7;
        const float* s = sm3[img];
        float v4 = 0.25f * ((s[(2*i4)*16 + 2*j4]   + s[(2*i4)*16 + 2*j4 + 1]) +
                            (s[(2*i4+1)*16 + 2*j4] + s[(2*i4+1)*16 + 2*j4 + 1]));
        float* d4 = (img ? b4 : a4) + (size_t)plane * 32 * 32;
        d4[(size_t)((y0 >> 3) + i4) * 32 + (x0 >> 3) + j4] = v4;
    }
}

// ---- Launch 3: levels 1-4, flat 4080 blocks ----
__global__ void __launch_bounds__(NT, 6)
ssim_rest_kernel(const float* __restrict__ a1, const float* __restrict__ b1,
                 const float* __restrict__ a2, const float* __restrict__ b2,
                 const float* __restrict__ a3, const float* __restrict__ b3,
                 const float* __restrict__ a4, const float* __restrict__ b4)
{
    __shared__ __align__(16) float2 s_uv[INH * INWP];
    __shared__ __align__(16) float4 h4[INH * TW];
    __shared__ float red_s[NT / 32], red_c[NT / 32];

    const int bid = blockIdx.x;
    int level, base;
    if (bid < 3072)      { level = 1; base = 0;    }
    else if (bid < 3840) { level = 2; base = 3072; }
    else if (bid < 4032) { level = 3; base = 3840; }
    else                 { level = 4; base = 4032; }
    const int side = 512 >> level;
    const int lw   = 4 - level;
    const int rel  = bid - base;
    const int plane = rel >> (2 * lw);
    const int rem   = rel & ((1 << (2 * lw)) - 1);
    const int x0 = (rem & ((1 << lw) - 1)) << 5;
    const int y0 = (rem >> lw) << 5;

    const float* img1 = (level == 1) ? a1 : (level == 2) ? a2 :
                        (level == 3) ? a3 : a4;
    const float* img2 = (level == 1) ? b1 : (level == 2) ? b2 :
                        (level == 3) ? b3 : b4;

    ssim_tile(img1 + (size_t)plane * side * side,
              img2 + (size_t)plane * side * side,
              nullptr, nullptr, plane,
              x0, y0, side, side, level,
              s_uv, h4, red_s, red_c);
}

// ---- Finalize: fp32, warp-parallel log, one exp. ----
__global__ void finalize_kernel(float* __restrict__ out)
{
    const int t = threadIdx.x;
    float term = 0.f;
    if (t < 5) {
        const float w[5] = {0.0448f, 0.2856f, 0.3001f, 0.2363f, 0.1333f};
        int side = 512 >> t;
        double cnt = (double)NPLANES * side * side;
        double v = (t < 4) ? (g_sums[2 * t + 1] / cnt)   // mcs
                           : (g_sums[2 * t] / cnt);      // mssim last level
        term = w[t] * __logf((float)v);
    }
    #pragma unroll
    for (int o = 16; o > 0; o >>= 1)
        term += __shfl_xor_sync(0xFFFFFFFFu, term, o);
    if (t == 0)
        out[0] = __expf(term);
}

extern "C" void kernel_launch(void* const* d_in, const int* in_sizes, int n_in,
                              void* d_out, int out_size)
{
    const float* img1 = (const float*)d_in[0];
    const float* img2 = (const float*)d_in[1];
    float* out = (float*)d_out;

    float *scr1 = nullptr, *scr2 = nullptr;
    cudaGetSymbolAddress((void**)&scr1, g_scr1);
    cudaGetSymbolAddress((void**)&scr2, g_scr2);
    void* sums_ptr = nullptr;
    cudaGetSymbolAddress(&sums_ptr, g_sums);

    float* a1 = scr1 + OFF_L1;  float* b1 = scr2 + OFF_L1;
    float* a2 = scr1 + OFF_L2;  float* b2 = scr2 + OFF_L2;
    float* a3 = scr1 + OFF_L3;  float* b3 = scr2 + OFF_L3;
    float* a4 = scr1 + OFF_L4;  float* b4 = scr2 + OFF_L4;

    cudaMemsetAsync(sums_ptr, 0, 10 * sizeof(double));

    ssim_l0_kernel<<<dim3(16, 16, NPLANES), NT>>>(img1, img2, a1, b1);
    pyramid2_kernel<<<dim3(4, 4, NPLANES), 256>>>(a1, b1, a2, b2, a3, b3, a4, b4);
    ssim_rest_kernel<<<4080, NT>>>(a1, b1, a2, b2, a3, b3, a4, b4);
    finalize_kernel<<<1, 32>>>(out);
}